// round 17
// baseline (speedup 1.0000x reference)
#include <cuda_runtime.h>
#include <cuda_fp16.h>
#include <cstdint>
#include <cstddef>

#define NODES 49152
#define FDIM  128
#define DTOT  9

// ---------------- device scratch (no allocation) ----------------
static __device__ __align__(16) __half g_Thi[(size_t)DTOT * NODES * FDIM];   // [d][n][u]
static __device__ __align__(16) __half g_Tlo[(size_t)DTOT * NODES * FDIM];
static __device__ __align__(16) float  g_TU [(size_t)DTOT * NODES * FDIM];   // [d][n][v]
static __device__ __align__(16) float  g_SU [(size_t)NODES * FDIM];          // su (p[:, :128])
static __device__ __align__(16) __half g_Whi[3 * 49152];                     // Wq[l]|Wk[l]|Wv[l]
static __device__ __align__(16) __half g_Wlo[3 * 49152];
static __device__ __align__(16) __half g_LShi[32768];                        // ls_w [256][128]
static __device__ __align__(16) __half g_LSlo[32768];
static __device__ __align__(16) __half g_LVhi[16384];                        // lvs_w [128][128]
static __device__ __align__(16) __half g_LVlo[16384];

// smem tile geometry: rows x 136 halves (272 B pitch)
#define TB    34816          // 128-row tile bytes
#define R_A   4096
#define R_B   77824
#define R_C   151552
#define SM_MAIN  221184      // R_C + 2*TB
#define LPITCH 264           // logit buffer pitch (floats)
#define THR   512

static __device__ __forceinline__ uint32_t smem_u32(const void* p) {
    uint32_t a;
    asm("{ .reg .u64 t; cvta.to.shared.u64 t, %1; cvt.u32.u64 %0, t; }" : "=r"(a) : "l"(p));
    return a;
}

// ---------------- mma.sync m16n8k16 fp16 -> fp32 ----------------
static __device__ __forceinline__ void mma16816(float* d,
    uint32_t a0, uint32_t a1, uint32_t a2, uint32_t a3, uint32_t b0, uint32_t b1) {
    asm volatile("mma.sync.aligned.m16n8k16.row.col.f32.f16.f16.f32 "
        "{%0,%1,%2,%3}, {%4,%5,%6,%7}, {%8,%9}, {%0,%1,%2,%3};"
        : "+f"(d[0]), "+f"(d[1]), "+f"(d[2]), "+f"(d[3])
        : "r"(a0), "r"(a1), "r"(a2), "r"(a3), "r"(b0), "r"(b1));
}
static __device__ __forceinline__ void ldsm4(uint32_t* r, uint32_t addr) {
    asm volatile("ldmatrix.sync.aligned.m8n8.x4.shared.b16 {%0,%1,%2,%3}, [%4];"
        : "=r"(r[0]), "=r"(r[1]), "=r"(r[2]), "=r"(r[3]) : "r"(addr));
}

// K=128 GEMM: warp tile 32x32, acc[2 mt][4 nt][4]. A,B smem u32 base addrs (pitched 272B, B stored [N][K]).
static __device__ __forceinline__ void gemm_pair(float* acc,
    uint32_t Abase, uint32_t Bbase, int m0, int n0, int lane) {
    const int lrow = lane & 15;
    const uint32_t lcb = (uint32_t)((lane >> 4) * 16);
    uint32_t aoff0 = Abase + (uint32_t)(m0 + lrow) * 272 + lcb;
    uint32_t aoff1 = aoff0 + 16 * 272;
    uint32_t boff0 = Bbase + (uint32_t)(n0 + lrow) * 272 + lcb;
    uint32_t boff1 = boff0 + 16 * 272;
    #pragma unroll
    for (int kt = 0; kt < 8; kt++) {
        uint32_t a0[4], a1[4], b0[4], b1[4];
        ldsm4(a0, aoff0 + kt * 32);
        ldsm4(a1, aoff1 + kt * 32);
        ldsm4(b0, boff0 + kt * 32);
        ldsm4(b1, boff1 + kt * 32);
        // b-frag per nt: nt0:(b0[0],b0[2]) nt1:(b0[1],b0[3]) nt2:(b1[0],b1[2]) nt3:(b1[1],b1[3])
        mma16816(acc + 0 * 4,  a0[0], a0[1], a0[2], a0[3], b0[0], b0[2]);
        mma16816(acc + 1 * 4,  a0[0], a0[1], a0[2], a0[3], b0[1], b0[3]);
        mma16816(acc + 2 * 4,  a0[0], a0[1], a0[2], a0[3], b1[0], b1[2]);
        mma16816(acc + 3 * 4,  a0[0], a0[1], a0[2], a0[3], b1[1], b1[3]);
        mma16816(acc + 4 * 4,  a1[0], a1[1], a1[2], a1[3], b0[0], b0[2]);
        mma16816(acc + 5 * 4,  a1[0], a1[1], a1[2], a1[3], b0[1], b0[3]);
        mma16816(acc + 6 * 4,  a1[0], a1[1], a1[2], a1[3], b1[0], b1[2]);
        mma16816(acc + 7 * 4,  a1[0], a1[1], a1[2], a1[3], b1[1], b1[3]);
    }
}
// split-precision: hi*hi + hi*lo + lo*hi
static __device__ __forceinline__ void gemm_split(float* acc,
    uint32_t Ah, uint32_t Al, uint32_t Bh, uint32_t Bl, int m0, int n0, int lane) {
    gemm_pair(acc, Ah, Bh, m0, n0, lane);
    gemm_pair(acc, Ah, Bl, m0, n0, lane);
    gemm_pair(acc, Al, Bh, m0, n0, lane);
}

// stage a [rows][128] half tile (row-major global) into pitched smem
static __device__ __forceinline__ void stage_h(char* dst, const __half* __restrict__ src,
                                               int rows, int tid, int nthr) {
    const uint4* s4 = reinterpret_cast<const uint4*>(src);
    for (int c = tid; c < rows * 16; c += nthr) {
        int row = c >> 4, cb = (c & 15) * 16;
        *reinterpret_cast<uint4*>(dst + row * 272 + cb) = s4[c];
    }
}
// stage [128][128] fp32 tile split into hi/lo fp16 pitched tiles
static __device__ __forceinline__ void stage_split_f32(char* dh, char* dl,
                                                       const float* __restrict__ src,
                                                       int tid, int nthr) {
    const float4* s4 = reinterpret_cast<const float4*>(src);
    for (int c = tid; c < 2048; c += nthr) {
        int row = c >> 4, cb = (c & 15) * 16;
        float4 x = s4[2 * c], y = s4[2 * c + 1];
        float v[8] = { x.x, x.y, x.z, x.w, y.x, y.y, y.z, y.w };
        uint32_t hw[4], lw[4];
        #pragma unroll
        for (int i = 0; i < 4; i++) {
            __half2 h2 = __floats2half2_rn(v[2 * i], v[2 * i + 1]);
            __half2 l2 = __floats2half2_rn(v[2 * i]     - __half2float(__low2half(h2)),
                                           v[2 * i + 1] - __half2float(__high2half(h2)));
            hw[i] = *reinterpret_cast<uint32_t*>(&h2);
            lw[i] = *reinterpret_cast<uint32_t*>(&l2);
        }
        *reinterpret_cast<uint4*>(dh + row * 272 + cb) = make_uint4(hw[0], hw[1], hw[2], hw[3]);
        *reinterpret_cast<uint4*>(dl + row * 272 + cb) = make_uint4(lw[0], lw[1], lw[2], lw[3]);
    }
}

// ---------------- K1: T [n][u][9] fp32 -> [d][n][u] fp16 hi/lo ----------------
__global__ __launch_bounds__(256) void k_splitT(const float* __restrict__ Tg) {
    extern __shared__ char sm[];
    __half* hi_s = reinterpret_cast<__half*>(sm);            // [9][32][128]
    __half* lo_s = hi_s + 9 * 32 * 128;
    const int tid = threadIdx.x;
    const int node0 = blockIdx.x * 32;
    const float4* g4 = reinterpret_cast<const float4*>(Tg + (size_t)node0 * 1152);
    #pragma unroll
    for (int it = 0; it < 36; it++) {
        int i = it * 256 + tid;
        float4 t = g4[i];
        float a[4] = { t.x, t.y, t.z, t.w };
        int e = i << 2;
        #pragma unroll
        for (int z = 0; z < 4; z++) {
            int ee = e + z;
            int nl = ee / 1152;
            int r  = ee - nl * 1152;
            int u  = r / 9;
            int d  = r - u * 9;
            __half h = __float2half_rn(a[z]);
            int idx = (d * 32 + nl) * 128 + u;
            hi_s[idx] = h;
            lo_s[idx] = __float2half_rn(a[z] - __half2float(h));
        }
    }
    __syncthreads();
    const uint4* h4 = reinterpret_cast<const uint4*>(hi_s);
    const uint4* l4 = reinterpret_cast<const uint4*>(lo_s);
    #pragma unroll
    for (int it = 0; it < 18; it++) {
        int j = it * 256 + tid;           // 4608 uint4
        int d = j >> 9;
        int w = j & 511;
        reinterpret_cast<uint4*>(g_Thi + ((size_t)d * NODES + node0) * 128)[w] = h4[j];
        reinterpret_cast<uint4*>(g_Tlo + ((size_t)d * NODES + node0) * 128)[w] = l4[j];
    }
}

// ---------------- K2: split weights (all L slices) ----------------
__global__ __launch_bounds__(256) void k_splitW(const float* __restrict__ Wq, const float* __restrict__ Wk,
                                                const float* __restrict__ Wv, const float* __restrict__ lsw,
                                                const float* __restrict__ lvw) {
    int idx = blockIdx.x * 256 + threadIdx.x;    // 0..196607
    float x;
    __half *dh, *dl;
    if (idx < 49152)       { x = Wq[idx];           dh = g_Whi + idx;           dl = g_Wlo + idx; }
    else if (idx < 98304)  { x = Wk[idx - 49152];   dh = g_Whi + idx;           dl = g_Wlo + idx; }
    else if (idx < 147456) { x = Wv[idx - 98304];   dh = g_Whi + idx;           dl = g_Wlo + idx; }
    else if (idx < 180224) { x = lsw[idx - 147456]; dh = g_LShi + idx - 147456; dl = g_LSlo + idx - 147456; }
    else                   { x = lvw[idx - 180224]; dh = g_LVhi + idx - 180224; dl = g_LVlo + idx - 180224; }
    __half h = __float2half_rn(x);
    *dh = h;
    *dl = __float2half_rn(x - __half2float(h));
}

// ---------------- K3: main mma kernel (384 CTAs x 128 nodes, 512 thr / 16 warps) ----------------
__global__ __launch_bounds__(THR, 1) void k_main(const float* __restrict__ Sg,
                                                 const float* __restrict__ w2,
                                                 const float* __restrict__ lsb,
                                                 const float* __restrict__ lvb,
                                                 float* __restrict__ out2) {
    extern __shared__ char sm[];
    float* w2s  = reinterpret_cast<float*>(sm);          // 384 floats
    float* lsbs = reinterpret_cast<float*>(sm + 1536);   // 256 floats
    float* lvbs = reinterpret_cast<float*>(sm + 2560);   // 128 floats
    const int tid  = threadIdx.x;
    const int lane = tid & 31;
    const int wid  = tid >> 5;
    const int g    = lane >> 2;
    const int tg   = lane & 3;
    const int m0   = (wid & 3) * 32;
    const int n0   = (wid >> 2) * 32;
    const int node0 = blockIdx.x * 128;
    const uint32_t sbase = smem_u32(sm);
    const uint32_t uRA = sbase + R_A, uRB = sbase + R_B, uRC = sbase + R_C;

    for (int i = tid; i < 768; i += THR) {
        if (i < 384)      w2s[i] = w2[i];
        else if (i < 640) lsbs[i - 384] = lsb[i - 384];
        else              lvbs[i - 640] = lvb[i - 640];
    }

    const int   dlo[3] = { 0, 1, 4 };
    const int   dhi[3] = { 1, 4, 9 };
    const float cfs[3] = { 0.0045105489780439515f,   // (1/sqrt3)/128
                           0.0026041666666666665f,   // (1/3)/128
                           0.0020171788261496963f }; // (1/sqrt15)/128

    float sF[32];
    #pragma unroll
    for (int i = 0; i < 32; i++) sF[i] = 0.f;

    // ===== q,k pass (per-irrep weights) =====
    #pragma unroll 1
    for (int l = 0; l < 3; l++) {
        stage_h(sm + R_A,      g_Whi +         l * 16384, 128, tid, THR);
        stage_h(sm + R_A + TB, g_Wlo +         l * 16384, 128, tid, THR);
        stage_h(sm + R_B,      g_Whi + 49152 + l * 16384, 128, tid, THR);
        stage_h(sm + R_B + TB, g_Wlo + 49152 + l * 16384, 128, tid, THR);
        const float cf = cfs[l];
        #pragma unroll 1
        for (int d = dlo[l]; d < dhi[l]; d++) {
            stage_h(sm + R_C,      g_Thi + ((size_t)d * NODES + node0) * 128, 128, tid, THR);
            stage_h(sm + R_C + TB, g_Tlo + ((size_t)d * NODES + node0) * 128, 128, tid, THR);
            __syncthreads();
            float qF[32], kF[32];
            #pragma unroll
            for (int i = 0; i < 32; i++) { qF[i] = 0.f; kF[i] = 0.f; }
            gemm_split(qF, uRC, uRC + TB, uRA, uRA + TB, m0, n0, lane);
            gemm_split(kF, uRC, uRC + TB, uRB, uRB + TB, m0, n0, lane);
            #pragma unroll
            for (int i = 0; i < 32; i++) sF[i] = fmaf(cf * qF[i], kF[i], sF[i]);
            __syncthreads();
        }
    }

    // ===== write s as hi/lo fp16 A-tile into R_A =====
    {
        uint32_t* WAh = reinterpret_cast<uint32_t*>(sm + R_A);
        uint32_t* WAl = reinterpret_cast<uint32_t*>(sm + R_A + TB);
        #pragma unroll
        for (int mt = 0; mt < 2; mt++)
        #pragma unroll
        for (int nt = 0; nt < 4; nt++) {
            float* e = sF + (mt * 4 + nt) * 4;
            int r0 = m0 + mt * 16 + g, r1 = r0 + 8;
            int cw = (n0 + nt * 8) / 2 + tg;
            __half2 h0 = __floats2half2_rn(e[0], e[1]);
            __half2 l0 = __floats2half2_rn(e[0] - __half2float(__low2half(h0)),
                                           e[1] - __half2float(__high2half(h0)));
            __half2 h1 = __floats2half2_rn(e[2], e[3]);
            __half2 l1 = __floats2half2_rn(e[2] - __half2float(__low2half(h1)),
                                           e[3] - __half2float(__high2half(h1)));
            WAh[r0 * 68 + cw] = *reinterpret_cast<uint32_t*>(&h0);
            WAl[r0 * 68 + cw] = *reinterpret_cast<uint32_t*>(&l0);
            WAh[r1 * 68 + cw] = *reinterpret_cast<uint32_t*>(&h1);
            WAl[r1 * 68 + cw] = *reinterpret_cast<uint32_t*>(&l1);
        }
    }
    // stage ls (256 rows): hi -> R_B, lo -> R_C
    stage_h(sm + R_B, g_LShi, 256, tid, THR);
    stage_h(sm + R_C, g_LSlo, 256, tid, THR);
    __syncthreads();

    // ===== logits GEMM (two N-halves) =====
    float lg0[32], lg1[32];
    #pragma unroll
    for (int i = 0; i < 32; i++) { lg0[i] = 0.f; lg1[i] = 0.f; }
    gemm_split(lg0, uRA, uRA + TB, uRB, uRC, m0, n0,       lane);
    gemm_split(lg1, uRA, uRA + TB, uRB, uRC, m0, n0 + 128, lane);
    __syncthreads();

    // dump logits fp32 into LB (pitch LPITCH) over R_B/R_C
    float* LB = reinterpret_cast<float*>(sm + R_B);
    #pragma unroll
    for (int mt = 0; mt < 2; mt++)
    #pragma unroll
    for (int nt = 0; nt < 4; nt++) {
        int r0 = m0 + mt * 16 + g, r1 = r0 + 8;
        int c0 = n0 + nt * 8 + tg * 2;
        float* e0 = lg0 + (mt * 4 + nt) * 4;
        float* e1 = lg1 + (mt * 4 + nt) * 4;
        LB[r0 * LPITCH + c0]       = e0[0];  LB[r0 * LPITCH + c0 + 1]       = e0[1];
        LB[r1 * LPITCH + c0]       = e0[2];  LB[r1 * LPITCH + c0 + 1]       = e0[3];
        LB[r0 * LPITCH + 128 + c0] = e1[0];  LB[r0 * LPITCH + 128 + c0 + 1] = e1[1];
        LB[r1 * LPITCH + 128 + c0] = e1[2];  LB[r1 * LPITCH + 128 + c0 + 1] = e1[3];
    }
    __syncthreads();

    // ===== softmax: 16 warps x 8 nodes; su -> g_SU, sd -> sd_s (R_A) =====
    float* sd_s = reinterpret_cast<float*>(sm + R_A);    // [128][136]
    #pragma unroll 1
    for (int r = 0; r < 8; r++) {
        int n = wid * 8 + r;
        float x[8], M = -1e30f;
        #pragma unroll
        for (int k8 = 0; k8 < 8; k8++) {
            x[k8] = LB[n * LPITCH + lane + 32 * k8] + lsbs[lane + 32 * k8];
            M = fmaxf(M, x[k8]);
        }
        #pragma unroll
        for (int off = 16; off > 0; off >>= 1)
            M = fmaxf(M, __shfl_xor_sync(0xffffffffu, M, off));
        float Ssum = 0.f;
        #pragma unroll
        for (int k8 = 0; k8 < 8; k8++) { x[k8] = __expf(x[k8] - M); Ssum += x[k8]; }
        #pragma unroll
        for (int off = 16; off > 0; off >>= 1)
            Ssum += __shfl_xor_sync(0xffffffffu, Ssum, off);
        float inv = 1.f / Ssum;
        #pragma unroll
        for (int k8 = 0; k8 < 4; k8++)
            g_SU[(size_t)(node0 + n) * 128 + lane + 32 * k8] = x[k8] * inv;
        #pragma unroll
        for (int k8 = 4; k8 < 8; k8++)
            sd_s[n * 136 + lane + 32 * (k8 - 4)] = x[k8] * inv;
    }
    __syncthreads();

    // ===== v pass (per-irrep Wv) =====
    const float INVF = 0.08838834764831845f;
    #pragma unroll 1
    for (int l = 0; l < 3; l++) {
        stage_h(sm + R_B,      g_Whi + 98304 + l * 16384, 128, tid, THR);
        stage_h(sm + R_B + TB, g_Wlo + 98304 + l * 16384, 128, tid, THR);
        const float* w2r = w2s + l * 128;
        #pragma unroll 1
        for (int d = dlo[l]; d < dhi[l]; d++) {
            stage_h(sm + R_C,      g_Thi + ((size_t)d * NODES + node0) * 128, 128, tid, THR);
            stage_h(sm + R_C + TB, g_Tlo + ((size_t)d * NODES + node0) * 128, 128, tid, THR);
            __syncthreads();
            float vF[32];
            #pragma unroll
            for (int i = 0; i < 32; i++) vF[i] = 0.f;
            gemm_split(vF, uRC, uRC + TB, uRB, uRB + TB, m0, n0, lane);
            float* tub = g_TU + ((size_t)d * NODES + node0) * 128;
            #pragma unroll
            for (int mt = 0; mt < 2; mt++)
            #pragma unroll
            for (int nt = 0; nt < 4; nt++) {
                float* e = vF + (mt * 4 + nt) * 4;
                int r0 = m0 + mt * 16 + g, r1 = r0 + 8;
                int c0 = n0 + nt * 8 + tg * 2;
                float wa = w2r[c0] * INVF, wb = w2r[c0 + 1] * INVF;
                float2 o0 = make_float2(e[0] * sd_s[r0 * 136 + c0] * wa,
                                        e[1] * sd_s[r0 * 136 + c0 + 1] * wb);
                float2 o1 = make_float2(e[2] * sd_s[r1 * 136 + c0] * wa,
                                        e[3] * sd_s[r1 * 136 + c0 + 1] * wb);
                *reinterpret_cast<float2*>(tub + (size_t)r0 * 128 + c0) = o0;
                *reinterpret_cast<float2*>(tub + (size_t)r1 * 128 + c0) = o1;
            }
            __syncthreads();
        }
    }

    // ===== out2 tail: su * silu(S @ lvw^T + b) =====
    stage_split_f32(sm + R_C, sm + R_C + TB, Sg + (size_t)node0 * 128, tid, THR);
    stage_h(sm + R_B,      g_LVhi, 128, tid, THR);
    stage_h(sm + R_B + TB, g_LVlo, 128, tid, THR);
    __syncthreads();
    {
        float zF[32];
        #pragma unroll
        for (int i = 0; i < 32; i++) zF[i] = 0.f;
        gemm_split(zF, uRC, uRC + TB, uRB, uRB + TB, m0, n0, lane);
        #pragma unroll
        for (int mt = 0; mt < 2; mt++)
        #pragma unroll
        for (int nt = 0; nt < 4; nt++) {
            float* e = zF + (mt * 4 + nt) * 4;
            int r0 = m0 + mt * 16 + g, r1 = r0 + 8;
            int c0 = n0 + nt * 8 + tg * 2;
            float b0 = lvbs[c0], b1 = lvbs[c0 + 1];
            float z0 = e[0] + b0, z1 = e[1] + b1;
            float z2 = e[2] + b0, z3 = e[3] + b1;
            float su0 = g_SU[(size_t)(node0 + r0) * 128 + c0];
            float su1 = g_SU[(size_t)(node0 + r0) * 128 + c0 + 1];
            float su2 = g_SU[(size_t)(node0 + r1) * 128 + c0];
            float su3 = g_SU[(size_t)(node0 + r1) * 128 + c0 + 1];
            float2 o0 = make_float2(su0 * (z0 / (1.f + __expf(-z0))),
                                    su1 * (z1 / (1.f + __expf(-z1))));
            float2 o1 = make_float2(su2 * (z2 / (1.f + __expf(-z2))),
                                    su3 * (z3 / (1.f + __expf(-z3))));
            *reinterpret_cast<float2*>(out2 + (size_t)(node0 + r0) * 128 + c0) = o0;
            *reinterpret_cast<float2*>(out2 + (size_t)(node0 + r1) * 128 + c0) = o1;
        }
    }
}

// ---------------- K5: g_TU [d][n][v] -> out [n][v][d] ----------------
__global__ __launch_bounds__(256) void k_outT(float* __restrict__ outT) {
    extern __shared__ char sm[];
    float* ts = reinterpret_cast<float*>(sm);   // [9][32][128]
    const int tid = threadIdx.x;
    const int node0 = blockIdx.x * 32;
    #pragma unroll
    for (int it = 0; it < 36; it++) {
        int j = it * 256 + tid;                 // 9216 float4
        int d = j >> 10;
        int w = j & 1023;
        reinterpret_cast<float4*>(ts)[j] =
            reinterpret_cast<const float4*>(g_TU + ((size_t)d * NODES + node0) * 128)[w];
    }
    __syncthreads();
    float4* o4 = reinterpret_cast<float4*>(outT + (size_t)node0 * 1152);
    #pragma unroll
    for (int it = 0; it < 36; it++) {
        int i = it * 256 + tid;
        int e = i << 2;
        int nl = e / 1152;
        int r  = e - nl * 1152;
        float o[4];
        #pragma unroll
        for (int z = 0; z < 4; z++) {
            int rr = r + z;
            int v_ = rr / 9;
            int d  = rr - v_ * 9;
            o[z] = ts[(d * 32 + nl) * 128 + v_];
        }
        o4[i] = make_float4(o[0], o[1], o[2], o[3]);
    }
}

// ---------------- launch ----------------
extern "C" void kernel_launch(void* const* d_in, const int* in_sizes, int n_in,
                              void* d_out, int out_size) {
    const float* Tg  = (const float*)d_in[0];
    const float* Sg  = (const float*)d_in[1];
    const float* Wq  = (const float*)d_in[2];
    const float* Wk  = (const float*)d_in[3];
    const float* Wv  = (const float*)d_in[4];
    const float* w2  = (const float*)d_in[5];
    const float* lsw = (const float*)d_in[6];
    const float* lsb = (const float*)d_in[7];
    const float* lvw = (const float*)d_in[8];
    const float* lvb = (const float*)d_in[9];

    float* out  = (float*)d_out;
    float* outT = out;
    float* out2 = out + (size_t)NODES * FDIM * DTOT;

    cudaFuncSetAttribute(k_splitT, cudaFuncAttributeMaxDynamicSharedMemorySize, 147456);
    cudaFuncSetAttribute(k_main,   cudaFuncAttributeMaxDynamicSharedMemorySize, SM_MAIN);
    cudaFuncSetAttribute(k_outT,   cudaFuncAttributeMaxDynamicSharedMemorySize, 147456);

    k_splitT<<<NODES / 32, 256, 147456>>>(Tg);
    k_splitW<<<768, 256>>>(Wq, Wk, Wv, lsw, lvw);
    k_main<<<NODES / 128, THR, SM_MAIN>>>(Sg, w2, lsb, lvb, out2);
    k_outT<<<NODES / 32, 256, 147456>>>(outT);
}